// round 7
// baseline (speedup 1.0000x reference)
#include <cuda_runtime.h>
#include <math.h>
#include <stdint.h>

#define Bdim 2
#define Tdim 4096
#define Cdim 2048
#define Hdim 64
#define Nheads 32
#define BT   (Bdim*Tdim)            // 8192
#define BTC  (Bdim*Tdim*Cdim)       // 16777216
#define BNHH (Bdim*Nheads*Hdim*Hdim) // 262144
#define CC   (Cdim*Cdim)            // 4194304
#define NCHUNK 64
#define CLEN  64
#define NHEADS_TOT 64

// ---------------- scratch ----------------
__device__ float g_dxprev[BTC];
__device__ float g_xmix[BTC];
__device__ float g_xr[BTC];
__device__ float g_xk[BTC];
__device__ float g_xv[BTC];
__device__ float g_xw[BTC];
__device__ float g_xv2[BTC];
__device__ float g_r[BTC];
__device__ float g_k[BTC];
__device__ float g_v[BTC];
__device__ float g_v2[BTC];
__device__ float g_w[BTC];
__device__ float g_y[BTC];
__device__ float g_xxx[BT*160];
__device__ float g_h[BT*64];
__device__ float g_wr[CC];
__device__ float g_wk[CC];
__device__ float g_wv[CC];
__device__ float g_wo[CC];
__device__ float g_S[NCHUNK*NHEADS_TOT*Hdim*Hdim];
__device__ float g_bst[NCHUNK*NHEADS_TOT*Hdim*Hdim];
__device__ float g_P[NCHUNK*NHEADS_TOT*Hdim];

// ---------------- helpers ----------------
__device__ __forceinline__ float f2tf32(float x) {
    uint32_t u;
    asm("cvt.rna.tf32.f32 %0, %1;" : "=r"(u) : "f"(x));
    return __uint_as_float(u);
}
__device__ __forceinline__ uint32_t smem_u32(const void* p) {
    uint32_t a;
    asm("{ .reg .u64 t; cvta.to.shared.u64 t, %1; cvt.u32.u64 %0, t; }" : "=r"(a) : "l"(p));
    return a;
}
__device__ __forceinline__ void cp16(uint32_t dst, const void* src) {
    asm volatile("cp.async.cg.shared.global [%0], [%1], 16;" :: "r"(dst), "l"(src));
}
__device__ __forceinline__ void mma_tf32(float* c, const uint32_t* a, const uint32_t* b) {
    asm volatile("mma.sync.aligned.m16n8k8.row.col.f32.tf32.tf32.f32 "
        "{%0,%1,%2,%3}, {%4,%5,%6,%7}, {%8,%9}, {%0,%1,%2,%3};"
        : "+f"(c[0]), "+f"(c[1]), "+f"(c[2]), "+f"(c[3])
        : "r"(a[0]), "r"(a[1]), "r"(a[2]), "r"(a[3]), "r"(b[0]), "r"(b[1]));
}

// ---------------- 0. tf32 rounding of all 4 weights, one launch ----------------
__global__ void cvtw_all(const float* __restrict__ s0, const float* __restrict__ s1,
                         const float* __restrict__ s2, const float* __restrict__ s3,
                         float* __restrict__ d0, float* __restrict__ d1,
                         float* __restrict__ d2, float* __restrict__ d3) {
    const float* s;
    float* d;
    int y = blockIdx.y;
    if (y == 0) { s = s0; d = d0; }
    else if (y == 1) { s = s1; d = d1; }
    else if (y == 2) { s = s2; d = d2; }
    else { s = s3; d = d3; }
    long i = ((long)blockIdx.x * 256 + threadIdx.x) * 4;
    float4 v = *(const float4*)(s + i);
    v.x = f2tf32(v.x); v.y = f2tf32(v.y); v.z = f2tf32(v.z); v.w = f2tf32(v.w);
    *(float4*)(d + i) = v;
}

// ---------------- 1. token shift + base mix ----------------
__global__ void prep_kernel(const float* __restrict__ x,
                            const float* __restrict__ shift,
                            const float* __restrict__ maa_x) {
    long idx = (long)blockIdx.x * 256 + threadIdx.x;
    int c = (int)(idx & (Cdim - 1));
    long tc = idx % ((long)Tdim * Cdim);
    float prev;
    if (tc < Cdim) {
        long b = idx / ((long)Tdim * Cdim);
        prev = shift[b * Cdim + c];
    } else {
        prev = x[idx - Cdim];
    }
    float xc = x[idx];
    float dx = prev - xc;
    g_dxprev[idx] = dx;
    g_xmix[idx] = xc + dx * maa_x[c];
}

// ---------------- 2. xxx = tanh(xmix @ maa_w1) ----------------
__global__ __launch_bounds__(160) void xxx_kernel(const float* __restrict__ w1) {
    __shared__ float sx[8][256];
    int m0 = blockIdx.x * 8;
    int tid = threadIdx.x;
    float acc[8];
    #pragma unroll
    for (int r = 0; r < 8; r++) acc[r] = 0.f;
    for (int kb = 0; kb < Cdim; kb += 256) {
        __syncthreads();
        for (int i = tid; i < 8 * 256; i += 160)
            sx[i >> 8][i & 255] = g_xmix[(long)(m0 + (i >> 8)) * Cdim + kb + (i & 255)];
        __syncthreads();
        for (int k = 0; k < 256; k++) {
            float w = w1[(kb + k) * 160 + tid];
            #pragma unroll
            for (int r = 0; r < 8; r++) acc[r] += sx[r][k] * w;
        }
    }
    #pragma unroll
    for (int r = 0; r < 8; r++) g_xxx[(m0 + r) * 160 + tid] = tanhf(acc[r]);
}

// ---------------- 3. mix coefficients ----------------
__global__ __launch_bounds__(256) void mixout_kernel(
    const float* __restrict__ x,
    const float* __restrict__ maa_r, const float* __restrict__ maa_k,
    const float* __restrict__ maa_v, const float* __restrict__ maa_w,
    const float* __restrict__ maa_v2, const float* __restrict__ w2) {
    __shared__ float sx[8][160];
    int m0 = blockIdx.x * 8;
    int tid = threadIdx.x;
    for (int i = tid; i < 8 * 160; i += 256)
        sx[i / 160][i % 160] = g_xxx[(m0 + i / 160) * 160 + (i % 160)];
    __syncthreads();
    for (int c = tid; c < Cdim; c += 256) {
        float mr = maa_r[c], mk = maa_k[c], mv = maa_v[c], mw = maa_w[c], mv2 = maa_v2[c];
        float acc[8][5];
        #pragma unroll
        for (int r = 0; r < 8; r++)
            #pragma unroll
            for (int f = 0; f < 5; f++) acc[r][f] = 0.f;
        #pragma unroll
        for (int f = 0; f < 5; f++) {
            #pragma unroll 8
            for (int l = 0; l < 32; l++) {
                float wv = w2[(f * 32 + l) * Cdim + c];
                #pragma unroll
                for (int r = 0; r < 8; r++) acc[r][f] += sx[r][f * 32 + l] * wv;
            }
        }
        #pragma unroll
        for (int r = 0; r < 8; r++) {
            long idx = (long)(m0 + r) * Cdim + c;
            float xc = x[idx];
            float dx = g_dxprev[idx];
            g_xr[idx]  = f2tf32(xc + dx * (mr  + acc[r][0]));
            g_xk[idx]  = f2tf32(xc + dx * (mk  + acc[r][1]));
            g_xv[idx]  = f2tf32(xc + dx * (mv  + acc[r][2]));
            g_xw[idx]  = xc + dx * (mw  + acc[r][3]);
            g_xv2[idx] = f2tf32(xc + dx * (mv2 + acc[r][4]));
        }
    }
}

// ---------------- 4. TF32 mma.sync GEMM: z-batched, GK=32, 3-stage, frag-pipelined ----------------
#define GM 256
#define GN 128
#define GK 32
#define GST 36
#define A_ST (GM*GST)
#define B_ST (GN*GST)
#define ST_FLOATS (A_ST+B_ST)
#define NBUF 3
#define GSMEM (ST_FLOATS*4*NBUF)
#define GEMM_N 2048
#define GEMM_K 2048

__global__ __launch_bounds__(256, 1) void tf32_gemm4(
    const float* __restrict__ A0, const float* __restrict__ A1,
    const float* __restrict__ A2, const float* __restrict__ A3,
    const float* __restrict__ B0, const float* __restrict__ B1,
    const float* __restrict__ B2,
    float* __restrict__ C0, float* __restrict__ C1,
    float* __restrict__ C2, float* __restrict__ C3) {
    const float* A; const float* B; float* C;
    {
        int z = blockIdx.z;
        if (z == 0)      { A = A0; B = B0; C = C0; }
        else if (z == 1) { A = A1; B = B1; C = C1; }
        else if (z == 2) { A = A2; B = B2; C = C2; }
        else             { A = A3; B = B2; C = C3; }
    }
    extern __shared__ float smf[];
    uint32_t sb = smem_u32(smf);
    int tid = threadIdx.x;
    int wid = tid >> 5, lane = tid & 31;
    int g = lane >> 2, tg = lane & 3;
    long bm = blockIdx.y * GM, bn = blockIdx.x * GN;
    int wm = (wid & 3) * 64, wn = (wid >> 2) * 64;

    int arow = tid;
    int brow = tid >> 1;
    int bcf = (tid & 1) * 16;

    float acc[4][8][4];
    #pragma unroll
    for (int i = 0; i < 4; i++)
        #pragma unroll
        for (int j = 0; j < 8; j++)
            #pragma unroll
            for (int q = 0; q < 4; q++) acc[i][j][q] = 0.f;

    const int kt = GEMM_K / GK;

    #define ISSUE(s)                                                              \
        do {                                                                      \
            int _buf = (s) % NBUF;                                                \
            const float* _ga = A + (bm + arow) * GEMM_K + (long)(s) * GK;         \
            uint32_t _da = sb + (_buf * ST_FLOATS + arow * GST) * 4;              \
            _Pragma("unroll")                                                     \
            for (int _i = 0; _i < 8; _i++)                                        \
                cp16(_da + _i * 16, _ga + _i * 4);                                \
            const float* _gb = B + (bn + brow) * GEMM_K + (long)(s) * GK + bcf;   \
            uint32_t _db = sb + (_buf * ST_FLOATS + A_ST + brow * GST + bcf) * 4; \
            _Pragma("unroll")                                                     \
            for (int _i = 0; _i < 4; _i++)                                        \
                cp16(_db + _i * 16, _gb + _i * 4);                                \
        } while (0)

    #define LDFRAG(fb, kk)                                                        \
        do {                                                                      \
            _Pragma("unroll")                                                     \
            for (int _i = 0; _i < 4; _i++) {                                      \
                int _r0 = wm + _i * 16 + g;                                       \
                af[fb][_i][0] = __float_as_uint(As[_r0 * GST + (kk) * 8 + tg]);   \
                af[fb][_i][1] = __float_as_uint(As[(_r0 + 8) * GST + (kk) * 8 + tg]); \
                af[fb][_i][2] = __float_as_uint(As[_r0 * GST + (kk) * 8 + tg + 4]);   \
                af[fb][_i][3] = __float_as_uint(As[(_r0 + 8) * GST + (kk) * 8 + tg + 4]); \
            }                                                                     \
            _Pragma("unroll")                                                     \
            for (int _j = 0; _j < 8; _j++) {                                      \
                int _c0 = wn + _j * 8 + g;                                        \
                bf[fb][_j][0] = __float_as_uint(Bs[_c0 * GST + (kk) * 8 + tg]);   \
                bf[fb][_j][1] = __float_as_uint(Bs[_c0 * GST + (kk) * 8 + tg + 4]); \
            }                                                                     \
        } while (0)

    ISSUE(0); asm volatile("cp.async.commit_group;");
    ISSUE(1); asm volatile("cp.async.commit_group;");

    for (int s = 0; s < kt; s++) {
        asm volatile("cp.async.wait_group 1;");
        __syncthreads();
        const float* As = smf + (s % NBUF) * ST_FLOATS;
        const float* Bs = As + A_ST;
        uint32_t af[2][4][4], bf[2][8][2];
        LDFRAG(0, 0);
        #pragma unroll
        for (int kk = 0; kk < 4; kk++) {
            if (kk < 3) LDFRAG((kk + 1) & 1, kk + 1);
            #pragma unroll
            for (int i = 0; i < 4; i++)
                #pragma unroll
                for (int j = 0; j < 8; j++)
                    mma_tf32(acc[i][j], af[kk & 1][i], bf[kk & 1][j]);
        }
        if (s + 2 < kt) ISSUE(s + 2);
        asm volatile("cp.async.commit_group;");
    }
    #undef ISSUE
    #undef LDFRAG

    #pragma unroll
    for (int i = 0; i < 4; i++) {
        #pragma unroll
        for (int j = 0; j < 8; j++) {
            long row = bm + wm + i * 16 + g;
            long col = bn + wn + j * 8 + tg * 2;
            *(float2*)(C + row * GEMM_N + col) = make_float2(acc[i][j][0], acc[i][j][1]);
            *(float2*)(C + (row + 8) * GEMM_N + col) = make_float2(acc[i][j][2], acc[i][j][3]);
        }
    }
}

// ---------------- 5. LoRA stage 1 ----------------
__global__ __launch_bounds__(256) void lora1_kernel(const float* __restrict__ A,
                                                    const float* __restrict__ W) {
    __shared__ float sa[8][256];
    int m0 = blockIdx.x * 8;
    int tid = threadIdx.x;
    int j = tid & 63;
    int rg = tid >> 6;
    float a0 = 0.f, a1 = 0.f;
    for (int kb = 0; kb < Cdim; kb += 256) {
        __syncthreads();
        for (int i = tid; i < 8 * 256; i += 256)
            sa[i >> 8][i & 255] = A[(long)(m0 + (i >> 8)) * Cdim + kb + (i & 255)];
        __syncthreads();
        for (int k = 0; k < 256; k++) {
            float w = W[(kb + k) * 64 + j];
            a0 += sa[rg][k] * w;
            a1 += sa[rg + 4][k] * w;
        }
    }
    g_h[(m0 + rg) * 64 + j] = tanhf(a0);
    g_h[(m0 + rg + 4) * 64 + j] = tanhf(a1);
}

// ---------------- 6. LoRA stage 2 ----------------
__global__ __launch_bounds__(256) void lora2_kernel(const float* __restrict__ W2,
                                                    float* __restrict__ out,
                                                    const float* __restrict__ biasvec,
                                                    int accumulate) {
    __shared__ float sh[8][64];
    int m0 = blockIdx.x * 8;
    int tid = threadIdx.x;
    for (int i = tid; i < 8 * 64; i += 256)
        sh[i >> 6][i & 63] = g_h[(m0 + (i >> 6)) * 64 + (i & 63)];
    __syncthreads();
    for (int c = tid; c < Cdim; c += 256) {
        float sv[8];
        #pragma unroll
        for (int r = 0; r < 8; r++) sv[r] = 0.f;
        #pragma unroll 8
        for (int l = 0; l < 64; l++) {
            float w = W2[l * Cdim + c];
            #pragma unroll
            for (int r = 0; r < 8; r++) sv[r] += sh[r][l] * w;
        }
        #pragma unroll
        for (int r = 0; r < 8; r++) {
            long idx = (long)(m0 + r) * Cdim + c;
            float base = accumulate ? out[idx] : biasvec[c];
            out[idx] = base + sv[r];
        }
    }
}

// ---------------- 8a. WKV phase 1 ----------------
__global__ __launch_bounds__(64) void wkv_phase1() {
    int blk = blockIdx.x;
    int bn = blk & 63;
    int c = blk >> 6;
    int b = bn >> 5, n = bn & 31;
    int j = threadIdx.x;

    float st[64];
    #pragma unroll
    for (int i = 0; i < 64; i++) st[i] = 0.f;
    float pj = 1.f;

    __shared__ float sk[64], sd[64];
    long base = ((long)b * Tdim + (long)c * CLEN) * Cdim + n * 64;

    for (int t = 0; t < CLEN; t++) {
        long idx = base + (long)t * Cdim + j;
        float d = expf(-expf(g_w[idx]));
        float kk = g_k[idx] * (1.0f - d);
        float cv = g_v[idx];
        sk[j] = kk; sd[j] = d;
        __syncthreads();
        #pragma unroll
        for (int i = 0; i < 64; i++) st[i] = st[i] * sd[i] + sk[i] * cv;
        pj *= d;
        __syncthreads();
    }

    long obase = ((long)c * 64 + bn) * 4096;
    #pragma unroll
    for (int i = 0; i < 64; i++) g_S[obase + i * 64 + j] = st[i];
    g_P[((long)c * 64 + bn) * 64 + j] = pj;
}

// ---------------- 8b. WKV phase 2 ----------------
__global__ __launch_bounds__(256) void wkv_combine(const float* __restrict__ state0,
                                                   float* __restrict__ stateout) {
    int bn = blockIdx.x;
    int tid = threadIdx.x;
    float stq[16];
    #pragma unroll
    for (int q = 0; q < 16; q++)
        stq[q] = state0[(long)bn * 4096 + tid + 256 * q];

    for (int c = 0; c < NCHUNK; c++) {
        long sbase = ((long)c * 64 + bn) * 4096;
        long pbase = ((long)c * 64 + bn) * 64;
        #pragma unroll
        for (int q = 0; q < 16; q++) {
            int e = tid + 256 * q;
            g_bst[sbase + e] = stq[q];
            stq[q] = g_P[pbase + (e >> 6)] * stq[q] + g_S[sbase + e];
        }
    }
    #pragma unroll
    for (int q = 0; q < 16; q++)
        stateout[(long)bn * 4096 + tid + 256 * q] = stq[q];
}

// ---------------- 8c. WKV phase 3 ----------------
__global__ __launch_bounds__(64) void wkv_phase3() {
    int blk = blockIdx.x;
    int bn = blk & 63;
    int c = blk >> 6;
    int b = bn >> 5, n = bn & 31;
    int j = threadIdx.x;

    float st[64];
    long ibase = ((long)c * 64 + bn) * 4096;
    #pragma unroll
    for (int i = 0; i < 64; i++) st[i] = g_bst[ibase + i * 64 + j];

    __shared__ float sr[64], sk[64], sd[64];
    long base = ((long)b * Tdim + (long)c * CLEN) * Cdim + n * 64;

    for (int t = 0; t < CLEN; t++) {
        long idx = base + (long)t * Cdim + j;
        float rr = g_r[idx];
        float d = expf(-expf(g_w[idx]));
        float kk = g_k[idx] * (1.0f - d);
        float cv = g_v[idx];
        float cv2 = g_v2[idx];
        sr[j] = rr; sk[j] = kk; sd[j] = d;
        __syncthreads();

        float y0 = 0.f, y1 = 0.f, y2 = 0.f, y3 = 0.f;
        #pragma unroll
        for (int i = 0; i < 64; i += 4) {
            y0 += sr[i]     * st[i];
            y1 += sr[i + 1] * st[i + 1];
            y2 += sr[i + 2] * st[i + 2];
            y3 += sr[i + 3] * st[i + 3];
        }
        g_y[idx] = ((y0 + y1) + (y2 + y3)) + cv2;

        #pragma unroll
        for (int i = 0; i < 64; i++) st[i] = st[i] * sd[i] + sk[i] * cv;
        __syncthreads();
    }
}

// ---------------- 9. layernorm ----------------
__global__ __launch_bounds__(256) void ln_kernel(const float* __restrict__ g,
                                                 const float* __restrict__ bb) {
    __shared__ float red[256];
    int m = blockIdx.x, tid = threadIdx.x;
    const float* row = g_y + (long)m * Cdim;
    float s1 = 0.f, s2 = 0.f;
    for (int c = tid; c < Cdim; c += 256) {
        float v = row[c];
        s1 += v;
        s2 += v * v;
    }
    red[tid] = s1;
    __syncthreads();
    for (int s = 128; s > 0; s >>= 1) {
        if (tid < s) red[tid] += red[tid + s];
        __syncthreads();
    }
    float mu = red[0] * (1.0f / Cdim);
    __syncthreads();
    red[tid] = s2;
    __syncthreads();
    for (int s = 128; s > 0; s >>= 1) {
        if (tid < s) red[tid] += red[tid + s];
        __syncthreads();
    }
    float var = red[0] * (1.0f / Cdim) - mu * mu;
    float rs = rsqrtf(var + 1e-5f);
    for (int c = tid; c < Cdim; c += 256)
        g_xmix[(long)m * Cdim + c] = f2tf32((row[c] - mu) * rs * g[c] + bb[c]);
}

// ---------------- 10. tail ----------------
__global__ void tail_kernel(const float* __restrict__ x, float* __restrict__ out2) {
    int i = blockIdx.x * 256 + threadIdx.x;
    if (i < Bdim * Cdim) {
        int b = i / Cdim, c = i % Cdim;
        out2[i] = x[((long)b * Tdim + (Tdim - 1)) * Cdim + c];
    }
}

// ---------------- host ----------------
static float* sym(const void* symbol) {
    void* p = nullptr;
    cudaGetSymbolAddress(&p, symbol);
    return (float*)p;
}

extern "C" void kernel_launch(void* const* d_in, const int* in_sizes, int n_in,
                              void* d_out, int out_size) {
    const float* x       = (const float*)d_in[0];
    const float* wkv0    = (const float*)d_in[1];
    const float* shift   = (const float*)d_in[2];
    const float* maa_x   = (const float*)d_in[3];
    const float* maa_r   = (const float*)d_in[4];
    const float* maa_k   = (const float*)d_in[5];
    const float* maa_v   = (const float*)d_in[6];
    const float* maa_w   = (const float*)d_in[7];
    const float* maa_v2  = (const float*)d_in[8];
    const float* maa_w1  = (const float*)d_in[9];
    const float* maa_w2  = (const float*)d_in[10];
    const float* tdecay  = (const float*)d_in[11];
    const float* dec_w1  = (const float*)d_in[12];
    const float* dec_w2  = (const float*)d_in[13];
    const float* v2_w1   = (const float*)d_in[14];
    const float* v2_w2   = (const float*)d_in[15];
    const float* Wr      = (const float*)d_in[16];
    const float* Wk      = (const float*)d_in[17];
    const float* Wv      = (const float*)d_in[18];
    const float* Wo      = (const float*)d_in[19];
    const float* ln_g    = (const float*)d_in[20];
    const float* ln_b    = (const float*)d_in[21];
    float* out = (float*)d_out;

    float* p_xr  = sym(g_xr);
    float* p_xk  = sym(g_xk);
    float* p_xv  = sym(g_xv);
    float* p_xw  = sym(g_xw);
    float* p_xv2 = sym(g_xv2);
    float* p_v2  = sym(g_v2);
    float* p_r   = sym(g_r);
    float* p_k   = sym(g_k);
    float* p_v   = sym(g_v);
    float* p_w   = sym(g_w);
    float* p_xm  = sym(g_xmix);
    float* p_wr  = sym(g_wr);
    float* p_wk  = sym(g_wk);
    float* p_wv  = sym(g_wv);
    float* p_wo  = sym(g_wo);

    static int attr_set = 0;
    if (!attr_set) {
        cudaFuncSetAttribute(tf32_gemm4, cudaFuncAttributeMaxDynamicSharedMemorySize, GSMEM);
        attr_set = 1;
    }

    dim3 ggrid4(GEMM_N / GN, BT / GM, 4);  // (16, 32, 4)
    dim3 ggrid1(GEMM_N / GN, BT / GM, 1);

    cvtw_all<<<dim3(CC / 1024, 4), 256>>>(Wr, Wk, Wv, Wo, p_wr, p_wk, p_wv, p_wo);
    prep_kernel<<<BTC / 256, 256>>>(x, shift, maa_x);
    xxx_kernel<<<BT / 8, 160>>>(maa_w1);
    mixout_kernel<<<BT / 8, 256>>>(x, maa_r, maa_k, maa_v, maa_w, maa_v2, maa_w2);

    tf32_gemm4<<<ggrid4, 256, GSMEM>>>(p_xr, p_xk, p_xv, p_xv2,
                                       p_wr, p_wk, p_wv,
                                       p_r, p_k, p_v, p_v2);

    lora1_kernel<<<BT / 8, 256>>>(p_xv2, v2_w1);
    lora2_kernel<<<BT / 8, 256>>>(v2_w2, p_v2, nullptr, 1);
    lora1_kernel<<<BT / 8, 256>>>(p_xw, dec_w1);
    lora2_kernel<<<BT / 8, 256>>>(dec_w2, p_w, tdecay, 0);

    wkv_phase1<<<NCHUNK * NHEADS_TOT, 64>>>();
    wkv_combine<<<NHEADS_TOT, 256>>>(wkv0, out + BTC);
    wkv_phase3<<<NCHUNK * NHEADS_TOT, 64>>>();

    ln_kernel<<<BT, 256>>>(ln_g, ln_b);
    tf32_gemm4<<<ggrid1, 256, GSMEM>>>(p_xm, p_xm, p_xm, p_xm,
                                       p_wo, p_wo, p_wo,
                                       out, out, out, out);

    tail_kernel<<<16, 256>>>(x, out + BTC + BNHH);
}